// round 1
// baseline (speedup 1.0000x reference)
#include <cuda_runtime.h>
#include <math.h>

#define DIMD 128
#define SAMP 12
#define WTS  132          // padded stride for transposed W1 (conflict-free)
#define ROWS 2            // rows per block
#define THREADS 128       // 4 warps: (row, s-half) = (warp>>1, warp&1)

typedef unsigned long long ull;

// ---- packed fp32x2 helpers (Blackwell-only; doubles fp32 FMA throughput) ----
__device__ __forceinline__ void ffma2(ull &acc, ull a, ull b) {
    asm("fma.rn.f32x2 %0, %1, %2, %0;" : "+l"(acc) : "l"(a), "l"(b));
}
__device__ __forceinline__ float2 unpack2(ull v) {
    float2 r;
    asm("mov.b64 {%0, %1}, %2;" : "=f"(r.x), "=f"(r.y) : "l"(v));
    return r;
}

// ---- shared memory layout (floats) ----
// Wt   : [128][WTS]   transposed W1 (d-contiguous per k row)
// nbs  : [ROWS][12][128]  raw neighbor rows (for epilogue weighted sum)
// ms   : [ROWS][12][128]  item ⊙ nb (GEMM A operand)
// its  : [ROWS][128]      item rows
// nws  : [ROWS][12] (+pad)
// avals: [ROWS][12] (+pad)
#define WT_ELEMS   (128*WTS)
#define NBS_OFF    WT_ELEMS
#define NBS_ELEMS  (ROWS*SAMP*DIMD)
#define MS_OFF     (NBS_OFF + NBS_ELEMS)
#define ITS_OFF    (MS_OFF + NBS_ELEMS)
#define ITS_ELEMS  (ROWS*DIMD)
#define NWS_OFF    (ITS_OFF + ITS_ELEMS)
#define AV_OFF     (NWS_OFF + 32)
#define SMEM_FLOATS (AV_OFF + 32)
#define SMEM_BYTES  (SMEM_FLOATS * 4)

// ---- scratch (no allocations allowed: device globals) ----
__device__ float g_a0[64*50*128];
__device__ float g_a1[64*600*128];
__device__ float g_b0[64*50*128];

// One generic attention-aggregate stage:
//   out[r,:] = sum_s softmax_s( w2 . lrelu( (item_r ⊙ nb_{r,s}) @ W1[0:D] + nw_{r,s} * W1[D,:] ) ) * nb_{r,s}
__global__ void __launch_bounds__(THREADS, 2)
agg_kernel(const float* __restrict__ item,   // [R, D]
           const float* __restrict__ nb,     // [R, S, D]
           const float* __restrict__ nw,     // [R, S]
           const float* __restrict__ w1,     // [D+1, D]
           const float* __restrict__ w2,     // [D]
           float* __restrict__ out,          // [R, D]
           int numRows)
{
    extern __shared__ float smem[];
    float* Wt    = smem;
    float* nbs   = smem + NBS_OFF;
    float* ms    = smem + MS_OFF;
    float* its   = smem + ITS_OFF;
    float* nws   = smem + NWS_OFF;
    float* avals = smem + AV_OFF;

    const int tid  = threadIdx.x;
    const int lane = tid & 31;
    const int warp = tid >> 5;   // 0..3
    const int rloc = warp >> 1;  // local row 0..1
    const int ws   = warp & 1;   // s-half: s in [ws*6, ws*6+6)

    // Load W1 transposed into smem (first 128 rows only; bias row handled in regs)
    for (int i = tid; i < 128*128; i += THREADS) {
        int d = i >> 7, k = i & 127;
        Wt[k*WTS + d] = w1[i];   // w1[d*128+k]
    }

    // Per-lane constants: k columns are {lane, lane+32, lane+64, lane+96}
    float w2r[4], biask[4];
    #pragma unroll
    for (int q = 0; q < 4; q++) {
        int k = lane + 32*q;
        w2r[q]   = w2[k];
        biask[q] = w1[128*128 + k];  // W1 row D (the nb_w column of the concat)
    }

    for (int g = blockIdx.x; g*ROWS < numRows; g += gridDim.x) {
        const int rowBase = g * ROWS;
        __syncthreads();  // smem reuse fence (also covers Wt on first iter)

        // Stage item rows + neighbor weights
        for (int i = tid; i < ROWS*DIMD; i += THREADS) {
            int r = i >> 7, row = rowBase + r;
            its[i] = (row < numRows) ? item[row*DIMD + (i & 127)] : 0.f;
        }
        if (tid < ROWS*SAMP) {
            int r = tid / SAMP, row = rowBase + r;
            nws[tid] = (row < numRows) ? nw[row*SAMP + tid % SAMP] : 0.f;
        }
        __syncthreads();

        // Stage nb (raw) and m = item ⊙ nb
        for (int i4 = tid; i4 < ROWS*SAMP*(DIMD/4); i4 += THREADS) {
            int r   = i4 / (SAMP*32);
            int rem = i4 - r*(SAMP*32);       // s*32 + d4
            int s   = rem >> 5;
            int d   = (rem & 31) * 4;
            int row = rowBase + r;
            float4 v = make_float4(0.f, 0.f, 0.f, 0.f);
            if (row < numRows)
                v = *(const float4*)&nb[row*(SAMP*DIMD) + s*DIMD + d];
            float4 itv = *(const float4*)&its[r*DIMD + d];
            *(float4*)&nbs[i4*4] = v;
            float4 m;
            m.x = v.x*itv.x; m.y = v.y*itv.y; m.z = v.z*itv.z; m.w = v.w*itv.w;
            *(float4*)&ms[i4*4] = m;
        }
        __syncthreads();

        const int row = rowBase + rloc;

        ull acc[6][4];
        #pragma unroll
        for (int s = 0; s < 6; s++)
            #pragma unroll
            for (int q = 0; q < 4; q++)
                acc[s][q] = 0ull;

        if (row < numRows) {
            const float* msrow = &ms[(rloc*SAMP + ws*6)*DIMD];
            // GEMM: y[s,k] = sum_d m[s,d] * W1[d,k], packed 2 fp32 FMAs/inst
            #pragma unroll 2
            for (int d = 0; d < DIMD; d += 4) {
                ulonglong2 wv0 = *(const ulonglong2*)&Wt[(lane +  0)*WTS + d];
                ulonglong2 wv1 = *(const ulonglong2*)&Wt[(lane + 32)*WTS + d];
                ulonglong2 wv2 = *(const ulonglong2*)&Wt[(lane + 64)*WTS + d];
                ulonglong2 wv3 = *(const ulonglong2*)&Wt[(lane + 96)*WTS + d];
                #pragma unroll
                for (int s = 0; s < 6; s++) {
                    ulonglong2 mp = *(const ulonglong2*)&msrow[s*DIMD + d];
                    ffma2(acc[s][0], mp.x, wv0.x); ffma2(acc[s][0], mp.y, wv0.y);
                    ffma2(acc[s][1], mp.x, wv1.x); ffma2(acc[s][1], mp.y, wv1.y);
                    ffma2(acc[s][2], mp.x, wv2.x); ffma2(acc[s][2], mp.y, wv2.y);
                    ffma2(acc[s][3], mp.x, wv3.x); ffma2(acc[s][3], mp.y, wv3.y);
                }
            }
            // bias + leaky_relu + dot(w2) + warp reduce over k
            #pragma unroll
            for (int s = 0; s < 6; s++) {
                float nwv = nws[rloc*SAMP + ws*6 + s];
                float v = 0.f;
                #pragma unroll
                for (int q = 0; q < 4; q++) {
                    float2 p = unpack2(acc[s][q]);
                    float y = p.x + p.y + nwv * biask[q];
                    y = (y >= 0.f) ? y : 0.2f * y;
                    v = fmaf(y, w2r[q], v);
                }
                #pragma unroll
                for (int off = 16; off > 0; off >>= 1)
                    v += __shfl_xor_sync(0xffffffffu, v, off);
                if (lane == 0) avals[rloc*SAMP + ws*6 + s] = v;
            }
        }
        __syncthreads();

        if (row < numRows) {
            // softmax over S=12 (redundant per lane: cheap)
            float a[SAMP];
            float mx = -1e30f;
            #pragma unroll
            for (int s = 0; s < SAMP; s++) { a[s] = avals[rloc*SAMP + s]; mx = fmaxf(mx, a[s]); }
            float sum = 0.f;
            #pragma unroll
            for (int s = 0; s < SAMP; s++) { a[s] = __expf(a[s] - mx); sum += a[s]; }
            float inv = 1.f / sum;
            // weighted sum of raw nb rows; this warp covers d in [ws*64, ws*64+64)
            int d0 = ws*64 + lane*2;
            float2 o = make_float2(0.f, 0.f);
            #pragma unroll
            for (int s = 0; s < SAMP; s++) {
                float al = a[s] * inv;
                float2 nb2 = *(const float2*)&nbs[(rloc*SAMP + s)*DIMD + d0];
                o.x = fmaf(al, nb2.x, o.x);
                o.y = fmaf(al, nb2.y, o.y);
            }
            *(float2*)&out[row*DIMD + d0] = o;
        }
    }
}

// Final gating: out = (1-sig)*h + sig*agg,  sig = sigmoid(h@w3 + agg@w4),
// agg = a0*s[0] + b0*s[1]
__global__ void __launch_bounds__(128)
final_kernel(const float* __restrict__ hidden,
             const float* __restrict__ a0,
             const float* __restrict__ b0,
             const float* __restrict__ w3,
             const float* __restrict__ w4,
             const float* __restrict__ sw,
             float* __restrict__ out,
             int numRows)
{
    __shared__ float hs[DIMD];
    __shared__ float as_[DIMD];
    const int tid = threadIdx.x;           // = k column
    const float s0 = sw[0], s1 = sw[1];

    for (int row = blockIdx.x; row < numRows; row += gridDim.x) {
        __syncthreads();
        {
            float h  = hidden[row*DIMD + tid];
            float ag = fmaf(a0[row*DIMD + tid], s0, b0[row*DIMD + tid] * s1);
            hs[tid]  = h;
            as_[tid] = ag;
        }
        __syncthreads();
        float z = 0.f;
        #pragma unroll 4
        for (int d = 0; d < DIMD; d++) {
            z = fmaf(hs[d],  w3[d*DIMD + tid], z);
            z = fmaf(as_[d], w4[d*DIMD + tid], z);
        }
        float sig = 1.f / (1.f + __expf(-z));
        out[row*DIMD + tid] = (1.f - sig) * hs[tid] + sig * as_[tid];
    }
}

extern "C" void kernel_launch(void* const* d_in, const int* in_sizes, int n_in,
                              void* d_out, int out_size)
{
    const float* hidden = (const float*)d_in[0];
    const float* nh1    = (const float*)d_in[1];
    const float* nh2    = (const float*)d_in[2];
    const float* nw0    = (const float*)d_in[3];
    const float* nw1    = (const float*)d_in[4];
    const float* w1     = (const float*)d_in[5];
    const float* w2     = (const float*)d_in[6];
    const float* w3     = (const float*)d_in[7];
    const float* w4     = (const float*)d_in[8];
    const float* sv     = (const float*)d_in[9];
    float* out = (float*)d_out;

    float *a0, *a1, *b0;
    cudaGetSymbolAddress((void**)&a0, g_a0);
    cudaGetSymbolAddress((void**)&a1, g_a1);
    cudaGetSymbolAddress((void**)&b0, g_b0);

    cudaFuncSetAttribute(agg_kernel, cudaFuncAttributeMaxDynamicSharedMemorySize, SMEM_BYTES);

    const int GRID = 296;  // 2 blocks/SM * 148 SMs

    // Stage A: agg(hidden, nh1, nw0) -> a0   [rows = 64*50]
    agg_kernel<<<GRID, THREADS, SMEM_BYTES>>>(hidden, nh1, nw0, w1, w2, a0, 64*50);
    // Stage B: agg(nh1, nh2, nw1) -> a1      [rows = 64*600]  (86% of FLOPs)
    agg_kernel<<<GRID, THREADS, SMEM_BYTES>>>(nh1, nh2, nw1, w1, w2, a1, 64*600);
    // Stage C: agg(a0, a1, nw0) -> b0        [rows = 64*50]
    agg_kernel<<<GRID, THREADS, SMEM_BYTES>>>(a0, a1, nw0, w1, w2, b0, 64*50);
    // Final gating
    final_kernel<<<GRID, 128>>>(hidden, a0, b0, w3, w4, sv, out, 64*50);
}

// round 4
// speedup vs baseline: 2.0599x; 2.0599x over previous
#include <cuda_runtime.h>
#include <cuda_bf16.h>
#include <cstdint>

#define DIMD 128
#define SAMP 12
#define RPT  10            // item rows per tile
#define MROWS 120          // GEMM rows per tile (padded to 128 in smem)
#define NT   256           // 8 warps; warp w owns GEMM rows [16w, 16w+16)

// ---- smem byte offsets (dynamic) ----
#define BHI_OFF   0          // W1^T bf16 hi  [128 n][128 k], swizzled   32768
#define BLO_OFF   32768      // W1^T bf16 lo                             32768
#define AHI_OFF   65536      // A bf16 hi [128 m][128 k], swizzled       32768
#define ALO_OFF   98304      //                                          32768
#define NBS_OFF   131072     // nb fp32 [120][128]                       61440
#define ITEM_OFF  192512     // item fp32 [10][128]                       5120
#define NW_OFF    197632     // 120 floats                                 512
#define LG_OFF    198144     // 120 logits                                 512
#define AL_OFF    198656     // 120 alphas                                 512
#define BIAS_OFF  199168     // 128 floats (W1 row D)                      512
#define W2_OFF    199680     // 128 floats                                 512
#define SMEM_TOTAL 200192

static __device__ __forceinline__ uint32_t smem_u32(const void* p) {
    uint32_t a;
    asm("{ .reg .u64 t; cvta.to.shared.u64 t, %1; cvt.u32.u64 %0, t; }" : "=r"(a) : "l"(p));
    return a;
}

static __device__ __forceinline__ void ldsm4(uint32_t &r0, uint32_t &r1, uint32_t &r2, uint32_t &r3,
                                             uint32_t addr) {
    asm volatile("ldmatrix.sync.aligned.m8n8.x4.shared.b16 {%0,%1,%2,%3}, [%4];"
                 : "=r"(r0), "=r"(r1), "=r"(r2), "=r"(r3) : "r"(addr));
}

static __device__ __forceinline__ void mma_bf16(float* d, const uint32_t* a, uint32_t b0, uint32_t b1) {
    asm volatile("mma.sync.aligned.m16n8k16.row.col.f32.bf16.bf16.f32 "
                 "{%0,%1,%2,%3}, {%4,%5,%6,%7}, {%8,%9}, {%0,%1,%2,%3};"
                 : "+f"(d[0]), "+f"(d[1]), "+f"(d[2]), "+f"(d[3])
                 : "r"(a[0]), "r"(a[1]), "r"(a[2]), "r"(a[3]), "r"(b0), "r"(b1));
}

// ---- scratch (no allocations allowed: device globals) ----
__device__ float g_a0[64*50*128];
__device__ float g_a1[64*600*128];
__device__ float g_b0[64*50*128];

// One attention-aggregate stage on tensor cores (legacy mma.sync path).
//   logits[r,k] = (item_r ⊙ nb_r) @ W1[0:D] + nw_r * W1[D,:]
//   out[r,:]    = softmax_s( w2 . leaky(logits) ) - weighted sum of nb rows
__global__ void __launch_bounds__(NT, 1)
agg_kernel(const float* __restrict__ item,   // [R, D]
           const float* __restrict__ nb,     // [R, S, D]
           const float* __restrict__ nw,     // [R, S]
           const float* __restrict__ w1,     // [D+1, D]
           const float* __restrict__ w2,     // [D]
           float* __restrict__ out,          // [R, D]
           int numRows)
{
    extern __shared__ __align__(128) char sm[];
    const uint32_t smb = smem_u32(sm);
    const int tid  = threadIdx.x;
    const int lane = tid & 31;
    const int warp = tid >> 5;          // 0..7, m-strip = rows [16w, 16w+16)

    // ---- one-time: B planes = hi/lo bf16 of W1^T[n][k], swizzled for ldmatrix ----
    for (int i = tid; i < DIMD*DIMD; i += NT) {
        int d = i >> 7, n = i & 127;                 // w1[d][n]
        float w = w1[i];
        __nv_bfloat16 hb = __float2bfloat16(w);
        __nv_bfloat16 lb = __float2bfloat16(w - __bfloat162float(hb));
        uint32_t off = (uint32_t)n*256u + ((uint32_t)(((d>>3) ^ (n & 7))) << 4) + ((uint32_t)(d & 7) << 1);
        *(__nv_bfloat16*)(sm + BHI_OFF + off) = hb;
        *(__nv_bfloat16*)(sm + BLO_OFF + off) = lb;
    }
    if (tid < DIMD) {
        ((float*)(sm + BIAS_OFF))[tid] = w1[DIMD*DIMD + tid];
        ((float*)(sm + W2_OFF))[tid]   = w2[tid];
    }

    // ---- per-lane constant pieces of fragment addressing ----
    // A (row-major m16k16): lanes 0-7 rows0-7/k-chunk0, 8-15 rows8-15/chunk0, 16-23 rows0-7/chunk1, 24-31 rows8-15/chunk1
    const int aRow   = warp*16 + (lane & 15);
    const uint32_t aRowOff = (uint32_t)aRow * 256u;
    const uint32_t aSwz    = (uint32_t)(aRow & 7);
    const uint32_t aCk     = (uint32_t)(lane >> 4);         // +0 / +1 chunk
    // B (W1^T[n][k]): lanes 0-7 n0-7/chunk0, 8-15 n0-7/chunk1, 16-23 n8-15/chunk0, 24-31 n8-15/chunk1
    const int nOff = (lane & 7) + (((lane >> 4) & 1) << 3);
    const uint32_t bRowOff = (uint32_t)nOff * 256u;
    const uint32_t bSwz    = (uint32_t)(lane & 7);          // == nOff & 7
    const uint32_t bCk     = (uint32_t)((lane >> 3) & 1);

    const uint32_t smbAhi = smb + AHI_OFF, smbAlo = smb + ALO_OFF;
    const uint32_t smbBhi = smb + BHI_OFF, smbBlo = smb + BLO_OFF;

    const float* nwf   = (const float*)(sm + NW_OFF);
    const float* biasf = (const float*)(sm + BIAS_OFF);
    const float* w2f   = (const float*)(sm + W2_OFF);
    const float* nbf   = (const float*)(sm + NBS_OFF);
    float* lgf = (float*)(sm + LG_OFF);
    float* alf = (float*)(sm + AL_OFF);

    const int numTiles = (numRows + RPT - 1) / RPT;

    for (int tile = blockIdx.x; tile < numTiles; tile += gridDim.x) {
        __syncthreads();   // guard smem reuse vs previous tile's epilogue readers
        const int rowBase = tile * RPT;

        // ---- stage item rows + neighbor weights ----
        for (int i = tid; i < RPT*32; i += NT)
            ((float4*)(sm + ITEM_OFF))[i] = ((const float4*)item)[(size_t)rowBase*32 + i];
        if (tid < MROWS)
            ((float*)(sm + NW_OFF))[tid] = nw[(size_t)rowBase*SAMP + tid];
        __syncthreads();

        // ---- nb -> fp32 plane; item⊙nb -> bf16 hi/lo swizzled A planes ----
        #pragma unroll 3
        for (int i = tid; i < MROWS*32; i += NT) {           // float4 granules
            int rs = i >> 5, j = i & 31;
            float4 v = ((const float4*)nb)[(size_t)rowBase*(SAMP*32) + i];
            *(float4*)(sm + NBS_OFF + (size_t)i*16) = v;
            float4 it = *(const float4*)(sm + ITEM_OFF + (size_t)(rs/SAMP)*512 + (size_t)j*16);
            float m0 = v.x*it.x, m1 = v.y*it.y, m2 = v.z*it.z, m3 = v.w*it.w;
            __nv_bfloat162 h01 = __floats2bfloat162_rn(m0, m1);
            __nv_bfloat162 h23 = __floats2bfloat162_rn(m2, m3);
            float2 f01 = __bfloat1622float2(h01);
            float2 f23 = __bfloat1622float2(h23);
            __nv_bfloat162 l01 = __floats2bfloat162_rn(m0 - f01.x, m1 - f01.y);
            __nv_bfloat162 l23 = __floats2bfloat162_rn(m2 - f23.x, m3 - f23.y);
            uint32_t off = (uint32_t)rs*256u + ((uint32_t)(((j>>1) ^ (rs & 7))) << 4) + ((uint32_t)(j & 1) << 3);
            *(__nv_bfloat162*)(sm + AHI_OFF + off)     = h01;
            *(__nv_bfloat162*)(sm + AHI_OFF + off + 4) = h23;
            *(__nv_bfloat162*)(sm + ALO_OFF + off)     = l01;
            *(__nv_bfloat162*)(sm + ALO_OFF + off + 4) = l23;
        }
        __syncthreads();

        // ---- MMA: D = Ahi@Bhi + Alo@Bhi + Ahi@Blo (fp32 accum) ----
        float d[64];
        #pragma unroll
        for (int i = 0; i < 64; i++) d[i] = 0.f;

        #pragma unroll
        for (int q = 0; q < 8; q++) {                        // k16 steps
            const uint32_t ack = ((uint32_t)(2*q) + aCk);
            const uint32_t aoff = aRowOff + (((ack ^ aSwz)) << 4);
            uint32_t ah[4], al[4];
            ldsm4(ah[0], ah[1], ah[2], ah[3], smbAhi + aoff);
            ldsm4(al[0], al[1], al[2], al[3], smbAlo + aoff);

            const uint32_t bck = ((uint32_t)(2*q) + bCk);
            const uint32_t bterm = bRowOff + (((bck ^ bSwz)) << 4);
            #pragma unroll
            for (int jp = 0; jp < 8; jp++) {                 // n-tile pairs (16 cols)
                uint32_t bh0, bh1, bh2, bh3, bl0, bl1, bl2, bl3;
                ldsm4(bh0, bh1, bh2, bh3, smbBhi + bterm + (uint32_t)jp*4096u);
                ldsm4(bl0, bl1, bl2, bl3, smbBlo + bterm + (uint32_t)jp*4096u);
                float* d0 = d + jp*8;
                float* d1 = d + jp*8 + 4;
                mma_bf16(d0, ah, bh0, bh1);
                mma_bf16(d1, ah, bh2, bh3);
                mma_bf16(d0, al, bh0, bh1);
                mma_bf16(d1, al, bh2, bh3);
                mma_bf16(d0, ah, bl0, bl1);
                mma_bf16(d1, ah, bl2, bl3);
            }
        }

        // ---- logits: bias*nw + leaky_relu + dot(w2), quad-reduce ----
        {
            const int r0 = warp*16 + (lane >> 2);
            const int r1 = r0 + 8;
            const int lq = lane & 3;
            const float nw0 = (r0 < MROWS) ? nwf[r0] : 0.f;
            const float nw1 = (r1 < MROWS) ? nwf[r1] : 0.f;
            float lg0 = 0.f, lg1 = 0.f;
            #pragma unroll
            for (int jp = 0; jp < 8; jp++) {
                #pragma unroll
                for (int t = 0; t < 2; t++) {
                    const int j = 2*jp + t;
                    const int c0 = j*8 + lq*2;
                    const float b0 = biasf[c0],   b1 = biasf[c0+1];
                    const float v0 = w2f[c0],     v1 = w2f[c0+1];
                    const float* db = d + jp*8 + t*4;
                    float y;
                    y = db[0] + nw0*b0; y = fmaxf(y, 0.f) + 0.2f*fminf(y, 0.f); lg0 = fmaf(y, v0, lg0);
                    y = db[1] + nw0*b1; y = fmaxf(y, 0.f) + 0.2f*fminf(y, 0.f); lg0 = fmaf(y, v1, lg0);
                    y = db[2] + nw1*b0; y = fmaxf(y, 0.f) + 0.2f*fminf(y, 0.f); lg1 = fmaf(y, v0, lg1);
                    y = db[3] + nw1*b1; y = fmaxf(y, 0.f) + 0.2f*fminf(y, 0.f); lg1 = fmaf(y, v1, lg1);
                }
            }
            lg0 += __shfl_xor_sync(0xffffffffu, lg0, 1);
            lg0 += __shfl_xor_sync(0xffffffffu, lg0, 2);
            lg1 += __shfl_xor_sync(0xffffffffu, lg1, 1);
            lg1 += __shfl_xor_sync(0xffffffffu, lg1, 2);
            if (lq == 0) {
                if (r0 < MROWS) lgf[r0] = lg0;
                if (r1 < MROWS) lgf[r1] = lg1;
            }
        }
        __syncthreads();

        // ---- softmax over S=12 per item row ----
        if (tid < RPT) {
            const float* lg = lgf + tid*SAMP;
            float l[SAMP], mx = -1e30f;
            #pragma unroll
            for (int s = 0; s < SAMP; s++) { l[s] = lg[s]; mx = fmaxf(mx, l[s]); }
            float sum = 0.f;
            #pragma unroll
            for (int s = 0; s < SAMP; s++) { l[s] = __expf(l[s] - mx); sum += l[s]; }
            float inv = 1.f / sum;
            #pragma unroll
            for (int s = 0; s < SAMP; s++) alf[tid*SAMP + s] = l[s] * inv;
        }
        __syncthreads();

        // ---- weighted sum of raw nb rows (thread = (half, col)) ----
        {
            const int col  = tid & 127;
            const int half = tid >> 7;
            #pragma unroll
            for (int rr = 0; rr < 5; rr++) {
                const int r = half*5 + rr;
                float acc = 0.f;
                #pragma unroll
                for (int s = 0; s < SAMP; s++)
                    acc = fmaf(alf[r*SAMP + s], nbf[(size_t)(r*SAMP + s)*DIMD + col], acc);
                const int row = rowBase + r;
                if (row < numRows) out[(size_t)row*DIMD + col] = acc;
            }
        }
    }
}

// Final gating: out = (1-sig)*h + sig*agg, sig = sigmoid(h@w3 + agg@w4),
// agg = a0*s0 + b0*s1.  8 rows/block share each w3/w4 column load.
__global__ void __launch_bounds__(128)
final_kernel(const float* __restrict__ hidden,
             const float* __restrict__ a0,
             const float* __restrict__ b0,
             const float* __restrict__ w3,
             const float* __restrict__ w4,
             const float* __restrict__ sw,
             float* __restrict__ out,
             int numRows)
{
    __shared__ float hs[8*DIMD];
    __shared__ float as_[8*DIMD];
    const int tid = threadIdx.x;
    const int rb  = blockIdx.x * 8;
    const float s0 = sw[0], s1 = sw[1];

    for (int i = tid; i < 8*DIMD; i += 128) {
        int row = rb + (i >> 7);
        float h = 0.f, ag = 0.f;
        if (row < numRows) {
            h  = hidden[(size_t)rb*DIMD + i];
            ag = fmaf(a0[(size_t)rb*DIMD + i], s0, b0[(size_t)rb*DIMD + i] * s1);
        }
        hs[i] = h; as_[i] = ag;
    }
    __syncthreads();

    float z[8];
    #pragma unroll
    for (int r = 0; r < 8; r++) z[r] = 0.f;
    #pragma unroll 4
    for (int d = 0; d < DIMD; d++) {
        float w3v = w3[d*DIMD + tid];
        float w4v = w4[d*DIMD + tid];
        #pragma unroll
        for (int r = 0; r < 8; r++)
            z[r] = fmaf(hs[r*DIMD + d], w3v, fmaf(as_[r*DIMD + d], w4v, z[r]));
    }
    #pragma unroll
    for (int r = 0; r < 8; r++) {
        int row = rb + r;
        if (row < numRows) {
            float sig = 1.f / (1.f + __expf(-z[r]));
            float h = hs[r*DIMD + tid], ag = as_[r*DIMD + tid];
            out[(size_t)row*DIMD + tid] = (1.f - sig)*h + sig*ag;
        }
    }
}

extern "C" void kernel_launch(void* const* d_in, const int* in_sizes, int n_in,
                              void* d_out, int out_size)
{
    const float* hidden = (const float*)d_in[0];
    const float* nh1    = (const float*)d_in[1];
    const float* nh2    = (const float*)d_in[2];
    const float* nw0    = (const float*)d_in[3];
    const float* nw1    = (const float*)d_in[4];
    const float* w1     = (const float*)d_in[5];
    const float* w2     = (const float*)d_in[6];
    const float* w3     = (const float*)d_in[7];
    const float* w4     = (const float*)d_in[8];
    const float* sv     = (const float*)d_in[9];
    float* out = (float*)d_out;

    float *a0, *a1, *b0;
    cudaGetSymbolAddress((void**)&a0, g_a0);
    cudaGetSymbolAddress((void**)&a1, g_a1);
    cudaGetSymbolAddress((void**)&b0, g_b0);

    cudaFuncSetAttribute(agg_kernel, cudaFuncAttributeMaxDynamicSharedMemorySize, SMEM_TOTAL);

    const int GRID = 148;   // 1 CTA/SM (200 KB smem), persistent tiles

    // Stage A: agg(hidden, nh1, nw0) -> a0   [3200 rows]
    agg_kernel<<<GRID, NT, SMEM_TOTAL>>>(hidden, nh1, nw0, w1, w2, a0, 64*50);
    // Stage B: agg(nh1, nh2, nw1) -> a1      [38400 rows, 86% of FLOPs]
    agg_kernel<<<GRID, NT, SMEM_TOTAL>>>(nh1, nh2, nw1, w1, w2, a1, 64*600);
    // Stage C: agg(a0, a1, nw0) -> b0        [3200 rows]
    agg_kernel<<<GRID, NT, SMEM_TOTAL>>>(a0, a1, nw0, w1, w2, b0, 64*50);
    // Final gating
    final_kernel<<<(64*50 + 7)/8, 128>>>(hidden, a0, b0, w3, w4, sv, out, 64*50);
}

// round 7
// speedup vs baseline: 2.6354x; 1.2793x over previous
#include <cuda_runtime.h>
#include <cuda_bf16.h>
#include <cstdint>

#define DIMD 128
#define SAMP 12
#define RPT  10            // item rows per tile (divides 3200 and 38400 exactly)
#define MROWS 120          // GEMM rows per tile (padded to 128 in the A planes)
#define NT   256           // 8 warps; warp w owns n-slice [16w, 16w+16)

// ---- smem byte offsets (dynamic) ----
#define NB0_OFF   0          // nb fp32 [120][128], buffer 0              61440
#define NB1_OFF   61440      // buffer 1                                  61440
#define AHI_OFF   122880     // A bf16 hi [128][128] swizzled             32768
#define ALO_OFF   155648     // A bf16 lo                                 32768
#define IT0_OFF   188416     // item fp32 [10][128] buf0                   5120
#define IT1_OFF   193536     // buf1                                       5120
#define NW0_OFF   198656     // 120 floats buf0                             512
#define NW1_OFF   199168     // buf1                                        512
#define LGP_OFF   199680     // logit partials [8 warps][128]              4096
#define LG_OFF    203776     // 120 logits                                  512
#define AL_OFF    204288     // 120 alphas                                  512
#define BIAS_OFF  204800     // 128 floats (W1 row D)                       512
#define W2_OFF    205312     // 128 floats                                  512
#define SMEM_TOTAL 205824
// W1^T bf16 hi/lo staging overlaps the NB region (read once before the loop)
#define BSTG_HI   0
#define BSTG_LO   32768

static __device__ __forceinline__ uint32_t smem_u32(const void* p) {
    uint32_t a;
    asm("{ .reg .u64 t; cvta.to.shared.u64 t, %1; cvt.u32.u64 %0, t; }" : "=r"(a) : "l"(p));
    return a;
}
static __device__ __forceinline__ void ldsm4(uint32_t &r0, uint32_t &r1, uint32_t &r2, uint32_t &r3,
                                             uint32_t addr) {
    asm volatile("ldmatrix.sync.aligned.m8n8.x4.shared.b16 {%0,%1,%2,%3}, [%4];"
                 : "=r"(r0), "=r"(r1), "=r"(r2), "=r"(r3) : "r"(addr));
}
static __device__ __forceinline__ void mma_bf16(float* d, const uint32_t* a, uint32_t b0, uint32_t b1) {
    asm volatile("mma.sync.aligned.m16n8k16.row.col.f32.bf16.bf16.f32 "
                 "{%0,%1,%2,%3}, {%4,%5,%6,%7}, {%8,%9}, {%0,%1,%2,%3};"
                 : "+f"(d[0]), "+f"(d[1]), "+f"(d[2]), "+f"(d[3])
                 : "r"(a[0]), "r"(a[1]), "r"(a[2]), "r"(a[3]), "r"(b0), "r"(b1));
}
static __device__ __forceinline__ void cp16(uint32_t smem_addr, const void* gmem) {
    asm volatile("cp.async.cg.shared.global [%0], [%1], 16;" :: "r"(smem_addr), "l"(gmem));
}
static __device__ __forceinline__ void cp_commit() {
    asm volatile("cp.async.commit_group;" ::: "memory");
}
static __device__ __forceinline__ void cp_wait0() {
    asm volatile("cp.async.wait_group 0;" ::: "memory");
}

// ---- scratch (no allocations allowed: device globals) ----
__device__ float g_a0[64*50*128];
__device__ float g_a1[64*600*128];
__device__ float g_b0[64*50*128];

// One attention-aggregate stage on tensor cores (mma.sync bf16, 3-term hi/lo).
__global__ void __launch_bounds__(NT, 1)
agg_kernel(const float* __restrict__ item,   // [R, D]
           const float* __restrict__ nb,     // [R, S, D]
           const float* __restrict__ nw,     // [R, S]
           const float* __restrict__ w1,     // [D+1, D]
           const float* __restrict__ w2,     // [D]
           float* __restrict__ out,          // [R, D]
           int numRows)                      // multiple of RPT
{
    extern __shared__ __align__(128) char sm[];
    const uint32_t smb = smem_u32(sm);
    const int tid  = threadIdx.x;
    const int lane = tid & 31;
    const int warp = tid >> 5;          // 0..7, owns output cols [16w, 16w+16)

    // ---- startup: stage W1^T hi/lo bf16 (swizzled) into the NB region ----
    for (int i = tid; i < DIMD*DIMD; i += NT) {
        int d = i >> 7, n = i & 127;                 // w1[d][n]
        float w = w1[i];
        __nv_bfloat16 hb = __float2bfloat16(w);
        __nv_bfloat16 lb = __float2bfloat16(w - __bfloat162float(hb));
        uint32_t off = (uint32_t)n*256u + ((uint32_t)(((d>>3) ^ (n & 7))) << 4) + ((uint32_t)(d & 7) << 1);
        *(__nv_bfloat16*)(sm + BSTG_HI + off) = hb;
        *(__nv_bfloat16*)(sm + BSTG_LO + off) = lb;
    }
    if (tid < DIMD) {
        ((float*)(sm + BIAS_OFF))[tid] = w1[DIMD*DIMD + tid];
        ((float*)(sm + W2_OFF))[tid]   = w2[tid];
    }
    __syncthreads();

    // ---- load B fragments for this warp's n-slice into registers (once) ----
    uint32_t bh[8][4], bl[8][4];
    {
        const uint32_t nRow = (uint32_t)(warp*16 + (lane & 7) + (((lane >> 4) & 1) << 3));
        const uint32_t bRowOff = nRow * 256u;
        const uint32_t bSwz = (uint32_t)(lane & 7);
        const uint32_t bCk  = (uint32_t)((lane >> 3) & 1);
        #pragma unroll
        for (int q = 0; q < 8; q++) {
            const uint32_t term = bRowOff + ((((uint32_t)(2*q) + bCk) ^ bSwz) << 4);
            ldsm4(bh[q][0], bh[q][1], bh[q][2], bh[q][3], smb + BSTG_HI + term);
            ldsm4(bl[q][0], bl[q][1], bl[q][2], bl[q][3], smb + BSTG_LO + term);
        }
    }
    __syncthreads();   // staging region free; becomes nb buffers

    // ---- zero A-plane rows 120..127 (never written per-tile) ----
    if (tid < 128) {
        *(float4*)(sm + AHI_OFF + 120*256 + tid*16) = make_float4(0.f,0.f,0.f,0.f);
    } else {
        *(float4*)(sm + ALO_OFF + 120*256 + (tid-128)*16) = make_float4(0.f,0.f,0.f,0.f);
    }

    const float* nwb[2]   = { (const float*)(sm + NW0_OFF), (const float*)(sm + NW1_OFF) };
    const float* nbb[2]   = { (const float*)(sm + NB0_OFF), (const float*)(sm + NB1_OFF) };
    const char*  itb[2]   = { sm + IT0_OFF, sm + IT1_OFF };
    const uint32_t nbOffB[2] = { NB0_OFF, NB1_OFF };
    const uint32_t itOffB[2] = { IT0_OFF, IT1_OFF };
    const uint32_t nwOffB[2] = { NW0_OFF, NW1_OFF };
    const float* biasf = (const float*)(sm + BIAS_OFF);
    const float* w2f   = (const float*)(sm + W2_OFF);
    float* lgpart = (float*)(sm + LGP_OFF);
    float* lgf    = (float*)(sm + LG_OFF);
    float* alf    = (float*)(sm + AL_OFF);

    // per-lane A-fragment addressing constants
    const uint32_t aLaneRow = (uint32_t)(lane & 15) * 256u;
    const uint32_t aCk      = (uint32_t)(lane >> 4);
    const uint32_t aSwz     = (uint32_t)(lane & 7);

    const int numTiles = numRows / RPT;

    // ---- preloop: prefetch first tile into buffer 0 ----
    {
        const int rowBase = blockIdx.x * RPT;
        const float4* nbsrc = (const float4*)nb + (size_t)rowBase*(SAMP*32);
        #pragma unroll
        for (int k = 0; k < 15; k++)
            cp16(smb + NB0_OFF + (uint32_t)(tid + k*NT)*16u, nbsrc + tid + k*NT);
        const float4* itsrc = (const float4*)item + (size_t)rowBase*32;
        cp16(smb + IT0_OFF + (uint32_t)tid*16u % 5120u + (tid < 320 ? 0u : 0u), itsrc + (tid % 320));
        // (item: 320 granules; thread 0..255 -> granule tid, 0..63 -> granule 256+tid)
        if (tid < 64) cp16(smb + IT0_OFF + (uint32_t)(256 + tid)*16u, itsrc + 256 + tid);
        const float4* nwsrc = (const float4*)(nw + (size_t)rowBase*SAMP);
        if (tid < 30) cp16(smb + NW0_OFF + (uint32_t)tid*16u, nwsrc + tid);
        cp_commit();
    }

    int cur = 0;
    for (int ti = blockIdx.x; ti < numTiles; ti += gridDim.x) {
        const int rowBase = ti * RPT;

        cp_wait0();
        __syncthreads();                 // buffer[cur] ready for all threads

        // ---- convert: A = bf16 hi/lo(item ⊙ nb) into swizzled planes ----
        {
            const float4* nbq = (const float4*)nbb[cur];
            const char* itc = itb[cur];
            #pragma unroll
            for (int k = 0; k < 15; k++) {
                const int i = tid + k*NT;
                const int rs = i >> 5, j = i & 31;
                float4 v  = nbq[i];
                float4 it = *(const float4*)(itc + (size_t)(rs/SAMP)*512 + (size_t)j*16);
                float m0 = v.x*it.x, m1 = v.y*it.y, m2 = v.z*it.z, m3 = v.w*it.w;
                __nv_bfloat162 h01 = __floats2bfloat162_rn(m0, m1);
                __nv_bfloat162 h23 = __floats2bfloat162_rn(m2, m3);
                float2 f01 = __bfloat1622float2(h01);
                float2 f23 = __bfloat1622float2(h23);
                __nv_bfloat162 l01 = __floats2bfloat162_rn(m0 - f01.x, m1 - f01.y);
                __nv_bfloat162 l23 = __floats2bfloat162_rn(m2 - f23.x, m3 - f23.y);
                uint32_t off = (uint32_t)rs*256u + ((uint32_t)(((j>>1) ^ (rs & 7))) << 4) + ((uint32_t)(j & 1) << 3);
                *(__nv_bfloat162*)(sm + AHI_OFF + off)     = h01;
                *(__nv_bfloat162*)(sm + AHI_OFF + off + 4) = h23;
                *(__nv_bfloat162*)(sm + ALO_OFF + off)     = l01;
                *(__nv_bfloat162*)(sm + ALO_OFF + off + 4) = l23;
            }
        }
        __syncthreads();                 // A planes ready; buffer[cur^1] free

        // ---- prefetch next tile into buffer[cur^1] (overlaps MMA+epilogue) ----
        {
            const int tn = ti + gridDim.x;
            if (tn < numTiles) {
                const int rb2 = tn * RPT;
                const uint32_t nbo = nbOffB[cur ^ 1], ito = itOffB[cur ^ 1], nwo = nwOffB[cur ^ 1];
                const float4* nbsrc = (const float4*)nb + (size_t)rb2*(SAMP*32);
                #pragma unroll
                for (int k = 0; k < 15; k++)
                    cp16(smb + nbo + (uint32_t)(tid + k*NT)*16u, nbsrc + tid + k*NT);
                const float4* itsrc = (const float4*)item + (size_t)rb2*32;
                cp16(smb + ito + (uint32_t)tid*16u, itsrc + tid);
                if (tid < 64) cp16(smb + ito + (uint32_t)(256 + tid)*16u, itsrc + 256 + tid);
                const float4* nwsrc = (const float4*)(nw + (size_t)rb2*SAMP);
                if (tid < 30) cp16(smb + nwo + (uint32_t)tid*16u, nwsrc + tid);
                cp_commit();
            }
        }

        // ---- MMA: warp computes D[:, 16w:16w+16] for all 128 rows ----
        float d[8][8];
        #pragma unroll
        for (int s = 0; s < 8; s++)
            #pragma unroll
            for (int i = 0; i < 8; i++) d[s][i] = 0.f;

        #pragma unroll
        for (int q = 0; q < 8; q++) {
            const uint32_t koff = ((((uint32_t)(2*q) + aCk) ^ aSwz) << 4);
            #pragma unroll
            for (int s = 0; s < 8; s++) {
                const uint32_t aoff = (uint32_t)s*4096u + aLaneRow + koff;
                uint32_t ah[4], al[4];
                ldsm4(ah[0], ah[1], ah[2], ah[3], smb + AHI_OFF + aoff);
                ldsm4(al[0], al[1], al[2], al[3], smb + ALO_OFF + aoff);
                mma_bf16(d[s]+0, ah, bh[q][0], bh[q][1]);
                mma_bf16(d[s]+4, ah, bh[q][2], bh[q][3]);
                mma_bf16(d[s]+0, al, bh[q][0], bh[q][1]);
                mma_bf16(d[s]+4, al, bh[q][2], bh[q][3]);
                mma_bf16(d[s]+0, ah, bl[q][0], bl[q][1]);
                mma_bf16(d[s]+4, ah, bl[q][2], bl[q][3]);
            }
        }

        // ---- logit partials: bias*nw + leaky + dot(w2) over this warp's 16 cols ----
        {
            const int lq = lane & 3;
            const int rq = lane >> 2;
            const float* nwf = nwb[cur];
            const int c0 = warp*16 + lq*2;
            const int c1 = c0 + 8;
            const float b00 = biasf[c0],  b01 = biasf[c0+1];
            const float b10 = biasf[c1],  b11 = biasf[c1+1];
            const float v00 = w2f[c0],    v01 = w2f[c0+1];
            const float v10 = w2f[c1],    v11 = w2f[c1+1];
            #pragma unroll
            for (int s = 0; s < 8; s++) {
                const int r0 = s*16 + rq;
                const int r1 = r0 + 8;
                const float nw0 = nwf[r0 < MROWS ? r0 : 0];
                const float nw1 = nwf[r1 < MROWS ? r1 : 0];
                float y, lg0 = 0.f, lg1 = 0.f;
                y = d[s][0] + nw0*b00; y = fmaxf(y,0.f) + 0.2f*fminf(y,0.f); lg0 = fmaf(y, v00, lg0);
                y = d[s][1] + nw0*b01; y = fmaxf(y,0.f) + 0.2f*fminf(y,0.f); lg0 = fmaf(y, v01, lg0);
                y = d[s][4] + nw0*b10; y = fmaxf(y,0.f) + 0.2f*fminf(y,0.f); lg0 = fmaf(y, v10, lg0);
                y = d[s][5] + nw0*b11; y = fmaxf(y,0.f) + 0.2f*fminf(y,0.f); lg0 = fmaf(y, v11, lg0);
                y = d[s][2] + nw1*b00; y = fmaxf(y,0.f) + 0.2f*fminf(y,0.f); lg1 = fmaf(y, v00, lg1);
                y = d[s][3] + nw1*b01; y = fmaxf(y,0.f) + 0.2f*fminf(y,0.f); lg1 = fmaf(y, v01, lg1);
                y = d[s][6] + nw1*b10; y = fmaxf(y,0.f) + 0.2f*fminf(y,0.f); lg1 = fmaf(y, v10, lg1);
                y = d[s][7] + nw1*b11; y = fmaxf(y,0.f) + 0.2f*fminf(y,0.f); lg1 = fmaf(y, v11, lg1);
                lg0 += __shfl_xor_sync(0xffffffffu, lg0, 1);
                lg0 += __shfl_xor_sync(0xffffffffu, lg0, 2);
                lg1 += __shfl_xor_sync(0xffffffffu, lg1, 1);
                lg1 += __shfl_xor_sync(0xffffffffu, lg1, 2);
                if (lq == 0) {
                    lgpart[warp*128 + r0] = lg0;
                    if (r1 < MROWS) lgpart[warp*128 + r1] = lg1;
                }
            }
        }
        __syncthreads();

        // ---- reduce partials across warps, then softmax over S=12 ----
        if (tid < MROWS) {
            float lg = 0.f;
            #pragma unroll
            for (int w = 0; w < 8; w++) lg += lgpart[w*128 + tid];
            lgf[tid] = lg;
        }
        __syncthreads();
        if (tid < RPT) {
            const float* lg = lgf + tid*SAMP;
            float l[SAMP], mx = -1e30f;
            #pragma unroll
            for (int s = 0; s < SAMP; s++) { l[s] = lg[s]; mx = fmaxf(mx, l[s]); }
            float sum = 0.f;
            #pragma unroll
            for (int s = 0; s < SAMP; s++) { l[s] = __expf(l[s] - mx); sum += l[s]; }
            float inv = 1.f / sum;
            #pragma unroll
            for (int s = 0; s < SAMP; s++) alf[tid*SAMP + s] = l[s] * inv;
        }
        __syncthreads();

        // ---- weighted sum of raw nb rows from the prefetch buffer ----
        {
            const int col  = tid & 127;
            const int half = tid >> 7;
            const float* nbf = nbb[cur];
            #pragma unroll
            for (int rr = 0; rr < 5; rr++) {
                const int r = half*5 + rr;
                float acc = 0.f;
                #pragma unroll
                for (int s = 0; s < SAMP; s++)
                    acc = fmaf(alf[r*SAMP + s], nbf[(size_t)(r*SAMP + s)*DIMD + col], acc);
                out[(size_t)(rowBase + r)*DIMD + col] = acc;
            }
        }
        __syncthreads();   // epilogue readers done before next convert overwrites
        cur ^= 1;
    }
}

// Final gating: out = (1-sig)*h + sig*agg, sig = sigmoid(h@w3 + agg@w4),
// agg = a0*s0 + b0*s1.  16 rows/block, 256 threads (2 row-groups of 8).
__global__ void __launch_bounds__(256)
final_kernel(const float* __restrict__ hidden,
             const float* __restrict__ a0,
             const float* __restrict__ b0,
             const float* __restrict__ w3,
             const float* __restrict__ w4,
             const float* __restrict__ sw,
             float* __restrict__ out,
             int numRows)
{
    __shared__ float hs[16*DIMD];
    __shared__ float as_[16*DIMD];
    const int tid = threadIdx.x;
    const int rb  = blockIdx.x * 16;
    const float s0 = sw[0], s1 = sw[1];

    for (int i = tid; i < 16*DIMD; i += 256) {
        float h  = hidden[(size_t)rb*DIMD + i];
        float ag = fmaf(a0[(size_t)rb*DIMD + i], s0, b0[(size_t)rb*DIMD + i] * s1);
        hs[i] = h; as_[i] = ag;
    }
    __syncthreads();

    const int col = tid & 127;
    const int g   = tid >> 7;          // row-group: rows [8g, 8g+8)
    float z[8];
    #pragma unroll
    for (int r = 0; r < 8; r++) z[r] = 0.f;
    #pragma unroll 8
    for (int d = 0; d < DIMD; d++) {
        float w3v = w3[d*DIMD + col];
        float w4v = w4[d*DIMD + col];
        #pragma unroll
        for (int r = 0; r < 8; r++)
            z[r] = fmaf(hs[(g*8+r)*DIMD + d], w3v, fmaf(as_[(g*8+r)*DIMD + d], w4v, z[r]));
    }
    #pragma unroll
    for (int r = 0; r < 8; r++) {
        const int row = rb + g*8 + r;
        float sig = 1.f / (1.f + __expf(-z[r]));
        float h = hs[(g*8+r)*DIMD + col], ag = as_[(g*8+r)*DIMD + col];
        out[(size_t)row*DIMD + col] = (1.f - sig)*h + sig*ag;
    }
}

extern "C" void kernel_launch(void* const* d_in, const int* in_sizes, int n_in,
                              void* d_out, int out_size)
{
    const float* hidden = (const float*)d_in[0];
    const float* nh1    = (const float*)d_in[1];
    const float* nh2    = (const float*)d_in[2];
    const float* nw0    = (const float*)d_in[3];
    const float* nw1    = (const float*)d_in[4];
    const float* w1     = (const float*)d_in[5];
    const float* w2     = (const float*)d_in[6];
    const float* w3     = (const float*)d_in[7];
    const float* w4     = (const float*)d_in[8];
    const float* sv     = (const float*)d_in[9];
    float* out = (float*)d_out;

    float *a0, *a1, *b0;
    cudaGetSymbolAddress((void**)&a0, g_a0);
    cudaGetSymbolAddress((void**)&a1, g_a1);
    cudaGetSymbolAddress((void**)&b0, g_b0);

    cudaFuncSetAttribute(agg_kernel, cudaFuncAttributeMaxDynamicSharedMemorySize, SMEM_TOTAL);

    const int GRID = 148;   // 1 CTA/SM (206 KB smem), persistent tiles

    // Stage A: agg(hidden, nh1, nw0) -> a0   [3200 rows]
    agg_kernel<<<GRID, NT, SMEM_TOTAL>>>(hidden, nh1, nw0, w1, w2, a0, 64*50);
    // Stage B: agg(nh1, nh2, nw1) -> a1      [38400 rows, 86% of FLOPs]
    agg_kernel<<<GRID, NT, SMEM_TOTAL>>>(nh1, nh2, nw1, w1, w2, a1, 64*600);
    // Stage C: agg(a0, a1, nw0) -> b0        [3200 rows]
    agg_kernel<<<GRID, NT, SMEM_TOTAL>>>(a0, a1, nw0, w1, w2, b0, 64*50);
    // Final gating
    final_kernel<<<(64*50)/16, 256>>>(hidden, a0, b0, w3, w4, sv, out, 64*50);
}